// round 3
// baseline (speedup 1.0000x reference)
#include <cuda_runtime.h>
#include <math.h>

// ---------------------------------------------------------------------------
// Constants: B=256, RANK=512, R4=128, R2=256
// ---------------------------------------------------------------------------

__device__ float g_latent[256 * 256];           // [ch][b]
__device__ float g_c[256 * 512 * 3];            // [b][r][3]
__device__ float g_x1[2 * 256 * 128 * 16];      // [s][b][ci][16]
__device__ float g_y2[2 * 256 * 256 * 32];      // [s][b][co][32] raw, t=31 pad
__device__ float g_psum[2 * 256 * 256];
__device__ float g_psq [2 * 256 * 256];
__device__ float g_sc[2 * 256];
__device__ float g_sh[2 * 256];
__device__ float g_o3[2 * 256 * 512 * 32];      // [s][b][r][32]

__device__ __forceinline__ void reduce2_256(float& s, float& ss) {
    __shared__ float rs[8], rss[8];
    #pragma unroll
    for (int o = 16; o > 0; o >>= 1) {
        s  += __shfl_down_sync(0xffffffffu, s,  o);
        ss += __shfl_down_sync(0xffffffffu, ss, o);
    }
    int wid = threadIdx.x >> 5, lane = threadIdx.x & 31;
    if (lane == 0) { rs[wid] = s; rss[wid] = ss; }
    __syncthreads();
    if (threadIdx.x < 32) {
        float a = lane < 8 ? rs[lane] : 0.f;
        float b = lane < 8 ? rss[lane] : 0.f;
        #pragma unroll
        for (int o = 4; o > 0; o >>= 1) {
            a += __shfl_down_sync(0xffffffffu, a, o);
            b += __shfl_down_sync(0xffffffffu, b, o);
        }
        if (lane == 0) { rs[0] = a; rss[0] = b; }
    }
    __syncthreads();
    s = rs[0]; ss = rss[0];
}

// ---------------------------------------------------------------------------
// Stage 1: latent = [lrelu(BN(noise@W.T+b),0.01) ; emb[label]], channel-major.
// ---------------------------------------------------------------------------
__global__ void k_latent(const float* __restrict__ noise, const int* __restrict__ label,
                         const float* __restrict__ lin_w, const float* __restrict__ lin_b,
                         const float* __restrict__ g,     const float* __restrict__ be,
                         const float* __restrict__ emb) {
    int j = blockIdx.x, b = threadIdx.x;
    if (j >= 128) {
        int jj = j - 128;
        g_latent[(128 + jj) * 256 + b] = emb[label[b] * 128 + jj];
        return;
    }
    __shared__ float wsm[100];
    if (b < 100) wsm[b] = lin_w[j * 100 + b];
    __syncthreads();
    float acc = lin_b[j];
    const float* nb = noise + b * 100;
    #pragma unroll 4
    for (int i = 0; i < 100; i++) acc += nb[i] * wsm[i];
    float s = acc, ss = acc * acc;
    reduce2_256(s, ss);
    float mean = s * (1.f / 256.f);
    float var  = ss * (1.f / 256.f) - mean * mean;
    float sc   = g[j] * rsqrtf(var + 1e-5f);
    float v    = (acc - mean) * sc + be[j];
    g_latent[j * 256 + b] = v >= 0.f ? v : 0.01f * v;
}

// ---------------------------------------------------------------------------
// Stage 2 merged: blocks [0,512) = c-branch (K=3, Cout=512);
//                 blocks [512,768) = h/w conv1 (K=16, Cout=128, s=bit7).
// thread = b; in-block BN + lrelu 0.2.
// ---------------------------------------------------------------------------
__global__ void __launch_bounds__(256)
k_conv1(const float* __restrict__ cW, const float* __restrict__ cB,
        const float* __restrict__ cG, const float* __restrict__ cBe,
        const float* __restrict__ hW, const float* __restrict__ hB,
        const float* __restrict__ hG, const float* __restrict__ hBe,
        const float* __restrict__ wW, const float* __restrict__ wB,
        const float* __restrict__ wG, const float* __restrict__ wBe) {
    int b = threadIdx.x;
    if (blockIdx.x < 512) {
        int co = blockIdx.x;
        __shared__ float ws[256 * 3];
        for (int i = b; i < 256 * 3; i += 256)
            ws[i] = cW[(i / 3) * 512 * 3 + co * 3 + (i % 3)];
        __syncthreads();
        float bv = cB[co];
        float a0 = bv, a1 = bv, a2 = bv;
        for (int ci = 0; ci < 256; ci++) {
            float x = g_latent[ci * 256 + b];
            a0 += x * ws[ci * 3 + 0];
            a1 += x * ws[ci * 3 + 1];
            a2 += x * ws[ci * 3 + 2];
        }
        float s = a0 + a1 + a2, ss = a0 * a0 + a1 * a1 + a2 * a2;
        reduce2_256(s, ss);
        const float invN = 1.f / 768.f;
        float mean = s * invN, var = ss * invN - mean * mean;
        float sc = cG[co] * rsqrtf(var + 1e-5f);
        float sh = cBe[co] - mean * sc;
        float v0 = a0 * sc + sh, v1 = a1 * sc + sh, v2 = a2 * sc + sh;
        float* o = g_c + (b * 512 + co) * 3;
        o[0] = v0 >= 0.f ? v0 : 0.2f * v0;
        o[1] = v1 >= 0.f ? v1 : 0.2f * v1;
        o[2] = v2 >= 0.f ? v2 : 0.2f * v2;
    } else {
        int bi = blockIdx.x - 512;
        int s_ = bi >> 7, co = bi & 127;
        const float* W  = s_ ? wW  : hW;
        const float* Bi = s_ ? wB  : hB;
        const float* G  = s_ ? wG  : hG;
        const float* Be = s_ ? wBe : hBe;
        __shared__ float ws[256 * 16];
        for (int i = b; i < 256 * 16; i += 256)
            ws[i] = W[(i >> 4) * 128 * 16 + co * 16 + (i & 15)];
        __syncthreads();
        float acc[16];
        float bv = Bi[co];
        #pragma unroll
        for (int t = 0; t < 16; t++) acc[t] = bv;
        for (int ci = 0; ci < 256; ci++) {
            float x = g_latent[ci * 256 + b];
            const float4* w4 = (const float4*)(ws + ci * 16);
            float4 wa = w4[0], wb = w4[1], wc = w4[2], wd = w4[3];
            acc[0] += x * wa.x; acc[1] += x * wa.y; acc[2]  += x * wa.z; acc[3]  += x * wa.w;
            acc[4] += x * wb.x; acc[5] += x * wb.y; acc[6]  += x * wb.z; acc[7]  += x * wb.w;
            acc[8] += x * wc.x; acc[9] += x * wc.y; acc[10] += x * wc.z; acc[11] += x * wc.w;
            acc[12]+= x * wd.x; acc[13]+= x * wd.y; acc[14] += x * wd.z; acc[15] += x * wd.w;
        }
        float s = 0.f, ss = 0.f;
        #pragma unroll
        for (int t = 0; t < 16; t++) { s += acc[t]; ss += acc[t] * acc[t]; }
        reduce2_256(s, ss);
        const float invN = 1.f / (256.f * 16.f);
        float mean = s * invN, var = ss * invN - mean * mean;
        float sc = G[co] * rsqrtf(var + 1e-5f);
        float sh = Be[co] - mean * sc;
        float* o = g_x1 + s_ * (256 * 128 * 16) + (b * 128 + co) * 16;
        #pragma unroll
        for (int t = 0; t < 16; t++) {
            float v = acc[t] * sc + sh;
            o[t] = v >= 0.f ? v : 0.2f * v;
        }
    }
}

// ---------------------------------------------------------------------------
// Stage 3: convT k=16: (B,128,16) -> (B,256,31). 2 batches per block.
// grid 256: s = blockIdx.x>>7, bpair = blockIdx.x&127. thread = co.
// ---------------------------------------------------------------------------
__global__ void __launch_bounds__(256, 2)
k_convT16(const float* __restrict__ hW, const float* __restrict__ hB,
          const float* __restrict__ wW, const float* __restrict__ wB) {
    int s_ = blockIdx.x >> 7, b0 = (blockIdx.x & 127) * 2;
    int co = threadIdx.x;
    __shared__ float X[2 * 2048];
    {
        const float4* xin = (const float4*)(g_x1 + s_ * (256 * 128 * 16) + b0 * 2048);
        float4* x4 = (float4*)X;
        #pragma unroll
        for (int i = 0; i < 4; i++) x4[co + 256 * i] = xin[co + 256 * i];
    }
    __syncthreads();

    const float* W  = (s_ ? wW : hW) + co * 16;
    const float* Bi = s_ ? wB : hB;
    float acc0[31], acc1[31];
    float bv = Bi[co];
    #pragma unroll
    for (int t = 0; t < 31; t++) { acc0[t] = bv; acc1[t] = bv; }

    for (int ci = 0; ci < 128; ci++) {
        const float4* wp = (const float4*)(W + ci * 4096);
        float4 wa = wp[0], wb = wp[1], wc = wp[2], wd = wp[3];
        float wr[16] = {wa.x, wa.y, wa.z, wa.w, wb.x, wb.y, wb.z, wb.w,
                        wc.x, wc.y, wc.z, wc.w, wd.x, wd.y, wd.z, wd.w};
        const float4* xa4 = (const float4*)(X + ci * 16);
        const float4* xb4 = (const float4*)(X + 2048 + ci * 16);
        #pragma unroll
        for (int s4 = 0; s4 < 4; s4++) {
            float4 xa = xa4[s4], xb = xb4[s4];
            float xs0[4] = {xa.x, xa.y, xa.z, xa.w};
            float xs1[4] = {xb.x, xb.y, xb.z, xb.w};
            #pragma unroll
            for (int j = 0; j < 4; j++) {
                int s2 = s4 * 4 + j;
                float x0 = xs0[j], x1 = xs1[j];
                #pragma unroll
                for (int k = 0; k < 16; k++) {
                    acc0[s2 + k] += x0 * wr[k];
                    acc1[s2 + k] += x1 * wr[k];
                }
            }
        }
    }
    float sum0 = 0.f, sq0 = 0.f, sum1 = 0.f, sq1 = 0.f;
    #pragma unroll
    for (int t = 0; t < 31; t++) {
        sum0 += acc0[t]; sq0 += acc0[t] * acc0[t];
        sum1 += acc1[t]; sq1 += acc1[t] * acc1[t];
    }
    float* o0 = g_y2 + s_ * (256 * 256 * 32) + (b0 * 256 + co) * 32;
    float* o1 = o0 + 256 * 32;
    #pragma unroll
    for (int t = 0; t < 31; t++) { o0[t] = acc0[t]; o1[t] = acc1[t]; }
    o0[31] = 0.f; o1[31] = 0.f;
    g_psum[s_ * 65536 + b0 * 256 + co]       = sum0;
    g_psq [s_ * 65536 + b0 * 256 + co]       = sq0;
    g_psum[s_ * 65536 + (b0 + 1) * 256 + co] = sum1;
    g_psq [s_ * 65536 + (b0 + 1) * 256 + co] = sq1;
}

// ---------------------------------------------------------------------------
// Stage 3b: reduce BN partials -> per-channel scale/shift.
// ---------------------------------------------------------------------------
__global__ void k_bnstat(const float* __restrict__ hG, const float* __restrict__ hBe,
                         const float* __restrict__ wG, const float* __restrict__ wBe) {
    int s_ = blockIdx.x, co = threadIdx.x;
    const float* G  = s_ ? wG  : hG;
    const float* Be = s_ ? wBe : hBe;
    float sum = 0.f, sq = 0.f;
    for (int b = 0; b < 256; b++) {
        sum += g_psum[s_ * 65536 + b * 256 + co];
        sq  += g_psq [s_ * 65536 + b * 256 + co];
    }
    const float invN = 1.f / (256.f * 31.f);
    float mean = sum * invN, var = sq * invN - mean * mean;
    float sc = G[co] * rsqrtf(var + 1e-5f);
    g_sc[s_ * 256 + co] = sc;
    g_sh[s_ * 256 + co] = Be[co] - mean * sc;
}

// ---------------------------------------------------------------------------
// Stage 4: convT k=2 + tanh: (B,256,31) -> (B,512,32).
// grid 512: s=blockIdx.x>>8, b=blockIdx.x&255. 256 threads; thread owns
// co = tid and tid+256 (same x row reused -> 4 FMA per LDS-float).
// ---------------------------------------------------------------------------
__global__ void __launch_bounds__(256, 2)
k_convT2(const float* __restrict__ hW, const float* __restrict__ hB,
         const float* __restrict__ wW, const float* __restrict__ wB) {
    int s_ = blockIdx.x >> 8, b = blockIdx.x & 255, tid = threadIdx.x;
    __shared__ float scs[256], shs[256];
    __shared__ float X[256 * 32];
    scs[tid] = g_sc[s_ * 256 + tid];
    shs[tid] = g_sh[s_ * 256 + tid];
    __syncthreads();
    const float4* in4 = (const float4*)(g_y2 + s_ * (256 * 256 * 32) + b * 8192);
    #pragma unroll
    for (int r = 0; r < 8; r++) {
        int i = tid + 256 * r;
        float4 v = in4[i];
        int ci = i >> 3;
        float sc = scs[ci], sh = shs[ci];
        float x0 = v.x * sc + sh; x0 = x0 >= 0.f ? x0 : 0.2f * x0;
        float x1 = v.y * sc + sh; x1 = x1 >= 0.f ? x1 : 0.2f * x1;
        float x2 = v.z * sc + sh; x2 = x2 >= 0.f ? x2 : 0.2f * x2;
        float x3 = v.w * sc + sh; x3 = x3 >= 0.f ? x3 : 0.2f * x3;
        if ((i & 7) == 7) x3 = 0.f;                    // t==31 pad
        float4 o; o.x = x0; o.y = x1; o.z = x2; o.w = x3;
        ((float4*)X)[i] = o;
    }
    __syncthreads();

    const float* W  = s_ ? wW : hW;
    const float* Bi = s_ ? wB : hB;
    float accA[32], accB[32];
    float bvA = Bi[tid], bvB = Bi[tid + 256];
    #pragma unroll
    for (int t = 0; t < 32; t++) { accA[t] = bvA; accB[t] = bvB; }

    for (int ci = 0; ci < 256; ci++) {
        const float2* w2 = (const float2*)(W + ci * 1024);
        float2 wA = w2[tid], wB2 = w2[tid + 256];
        const float4* x4 = (const float4*)(X + ci * 32);
        float xp = 0.f;                                // x[-1]
        #pragma unroll
        for (int q = 0; q < 8; q++) {
            float4 xv = x4[q];
            int t = q * 4;
            accA[t]     += xv.x * wA.x + xp   * wA.y;
            accB[t]     += xv.x * wB2.x + xp  * wB2.y;
            accA[t + 1] += xv.y * wA.x + xv.x * wA.y;
            accB[t + 1] += xv.y * wB2.x + xv.x * wB2.y;
            accA[t + 2] += xv.z * wA.x + xv.y * wA.y;
            accB[t + 2] += xv.z * wB2.x + xv.y * wB2.y;
            accA[t + 3] += xv.w * wA.x + xv.z * wA.y;
            accB[t + 3] += xv.w * wB2.x + xv.z * wB2.y;
            xp = xv.w;
        }
    }
    float* oA = g_o3 + s_ * (256 * 512 * 32) + (b * 512 + tid) * 32;
    float* oB = oA + 256 * 32;
    #pragma unroll
    for (int t = 0; t < 32; t++) { oA[t] = tanhf(accA[t]); oB[t] = tanhf(accB[t]); }
}

// ---------------------------------------------------------------------------
// Stage 5: out[b,ch,y,x] = sum_r c[b,r,ch]*coef[r] * h[b,r,y] * w[b,r,x]
// ---------------------------------------------------------------------------
__global__ void k_final(const float* __restrict__ coef, float* __restrict__ out) {
    int b = blockIdx.x, tid = threadIdx.x;
    int y = tid >> 5, x = tid & 31;
    __shared__ float shh[32 * 32], shw[32 * 32], shc[32 * 3];
    float a0 = 0.f, a1 = 0.f, a2 = 0.f;
    int ri = tid >> 5, rp = tid & 31;
    for (int r0 = 0; r0 < 512; r0 += 32) {
        shh[tid] = g_o3[                 (b * 512 + r0 + ri) * 32 + rp];
        shw[tid] = g_o3[256 * 512 * 32 + (b * 512 + r0 + ri) * 32 + rp];
        if (tid < 96) {
            int rr = tid / 3, c3 = tid % 3;
            shc[tid] = g_c[(b * 512 + r0 + rr) * 3 + c3] * coef[r0 + rr];
        }
        __syncthreads();
        #pragma unroll
        for (int i = 0; i < 32; i++) {
            float p = shh[i * 32 + y] * shw[i * 32 + x];
            a0 += shc[i * 3 + 0] * p;
            a1 += shc[i * 3 + 1] * p;
            a2 += shc[i * 3 + 2] * p;
        }
        __syncthreads();
    }
    out[((b * 3 + 0) * 32 + y) * 32 + x] = a0;
    out[((b * 3 + 1) * 32 + y) * 32 + x] = a1;
    out[((b * 3 + 2) * 32 + y) * 32 + x] = a2;
}

// ---------------------------------------------------------------------------
extern "C" void kernel_launch(void* const* d_in, const int* in_sizes, int n_in,
                              void* d_out, int out_size) {
    const float* noise  = (const float*)d_in[0];
    const int*   label  = (const int*)  d_in[1];
    const float* lin_w  = (const float*)d_in[2];
    const float* lin_b  = (const float*)d_in[3];
    const float* bn0_g  = (const float*)d_in[4];
    const float* bn0_b  = (const float*)d_in[5];
    const float* emb    = (const float*)d_in[6];
    const float* c_w1   = (const float*)d_in[7];
    const float* c_b1   = (const float*)d_in[8];
    const float* c_g1   = (const float*)d_in[9];
    const float* c_be1  = (const float*)d_in[10];
    const float* h_w1   = (const float*)d_in[11];
    const float* h_b1   = (const float*)d_in[12];
    const float* h_g1   = (const float*)d_in[13];
    const float* h_be1  = (const float*)d_in[14];
    const float* h_w2   = (const float*)d_in[15];
    const float* h_b2   = (const float*)d_in[16];
    const float* h_g2   = (const float*)d_in[17];
    const float* h_be2  = (const float*)d_in[18];
    const float* h_w3   = (const float*)d_in[19];
    const float* h_b3   = (const float*)d_in[20];
    const float* w_w1   = (const float*)d_in[21];
    const float* w_b1   = (const float*)d_in[22];
    const float* w_g1   = (const float*)d_in[23];
    const float* w_be1  = (const float*)d_in[24];
    const float* w_w2   = (const float*)d_in[25];
    const float* w_b2   = (const float*)d_in[26];
    const float* w_g2   = (const float*)d_in[27];
    const float* w_be2  = (const float*)d_in[28];
    const float* w_w3   = (const float*)d_in[29];
    const float* w_b3   = (const float*)d_in[30];
    const float* coef   = (const float*)d_in[31];
    float* out = (float*)d_out;

    k_latent <<<256, 256>>>(noise, label, lin_w, lin_b, bn0_g, bn0_b, emb);
    k_conv1  <<<768, 256>>>(c_w1, c_b1, c_g1, c_be1,
                            h_w1, h_b1, h_g1, h_be1,
                            w_w1, w_b1, w_g1, w_be1);
    k_convT16<<<256, 256>>>(h_w2, h_b2, w_w2, w_b2);
    k_bnstat <<<2,   256>>>(h_g2, h_be2, w_g2, w_be2);
    k_convT2 <<<512, 256>>>(h_w3, h_b3, w_w3, w_b3);
    k_final  <<<256, 1024>>>(coef, out);
}